// round 17
// baseline (speedup 1.0000x reference)
#include <cuda_runtime.h>
#include <cstdint>

// SoftReordering, R16: two-kernel split, barrier-free streaming.
//   K1 (gates): CTA per t, 4 batch-groups x 64 e-threads, direct LDG of the
//     unique weight[t] slice (no smem staging, no per-phase barriers); the
//     16x (cp_wait -> barrier) serialization of R8 is gone. Logits reduced
//     once, sigmoid applied, gates -> 459KB __device__ scratch.
//   K2 (out): warp sliding-window over t: one new x float4 per t, 7-tap
//     window in registers -> x read exactly once (was 7x).

#define BB   16
#define SSEQ 1024
#define EE   1024
#define WW   7
#define WE   7168

__device__ float g_gates[BB * SSEQ * 8];   // [b][t][8] (v padded to 8)

__device__ __forceinline__ void ffma2(unsigned long long& d,
                                      unsigned long long a,
                                      unsigned long long b) {
    asm("fma.rn.f32x2 %0, %1, %2, %3;" : "=l"(d) : "l"(a), "l"(b), "l"(d));
}
__device__ __forceinline__ unsigned long long pack2(float lo, float hi) {
    unsigned long long p;
    asm("mov.b64 %0, {%1, %2};" : "=l"(p) : "f"(lo), "f"(hi));
    return p;
}
__device__ __forceinline__ unsigned long long pack_dup(float g) {
    unsigned long long p;
    asm("mov.b64 %0, {%1, %1};" : "=l"(p) : "f"(g));
    return p;
}
__device__ __forceinline__ float2 unpack2(unsigned long long v) {
    float2 r;
    asm("mov.b64 {%0, %1}, %2;" : "=f"(r.x), "=f"(r.y) : "l"(v));
    return r;
}
__device__ __forceinline__ unsigned long long add2(unsigned long long a,
                                                   unsigned long long b) {
    unsigned long long d;
    asm("add.rn.f32x2 %0, %1, %2;" : "=l"(d) : "l"(a), "l"(b));
    return d;
}
__device__ __forceinline__ unsigned long long shfl_xor_u64(unsigned long long v,
                                                           int m) {
    uint32_t lo = (uint32_t)v, hi = (uint32_t)(v >> 32);
    lo = __shfl_xor_sync(0xffffffffu, lo, m);
    hi = __shfl_xor_sync(0xffffffffu, hi, m);
    return ((unsigned long long)hi << 32) | lo;
}
__device__ __forceinline__ float tanh_ap(float x) {
    float r;
    asm("tanh.approx.f32 %0, %1;" : "=f"(r) : "f"(x));
    return r;
}

// ----------------------------------------------------------------------
// Kernel 1: gates[b][t][v] = sigmoid(bias + sum_{w,e} x[b,t+w-3,e]*W[t,v,w,e])
// ----------------------------------------------------------------------
__global__ void __launch_bounds__(256, 2)
gates_kernel(const float* __restrict__ x,
             const float* __restrict__ wgt,
             const float* __restrict__ bias) {
    const int t    = blockIdx.x;
    const int tid  = threadIdx.x;
    const int lane = tid & 31;
    const int warp = tid >> 5;
    const int et   = tid & 63;            // e-thread (64 per batch group)
    const int bg   = tid >> 6;            // batch group (4 batches)
    const int b0   = bg << 2;

    __shared__ unsigned long long s_red[8 * 14];   // [warp][v*2+pr]

    unsigned long long acc[7][2];         // [v][pair] f32x2 over batch pairs
#pragma unroll
    for (int v = 0; v < 7; ++v) { acc[v][0] = 0ull; acc[v][1] = 0ull; }

    const float* wt = wgt + (size_t)t * 7 * WE;    // weight[t][v][w*E+e]

    for (int w = 0; w < 7; ++w) {
        const int r = t + w - 3;
        if (r < 0 || r >= SSEQ) continue;          // PAD_VAL = 0 contribution
        const float* xr = x + ((size_t)b0 * SSEQ + r) * EE;
        const float* wr = wt + w * EE;
#pragma unroll
        for (int c = 0; c < 4; ++c) {
            const int e = (c << 8) + (et << 2);
            float4 xv[4];
#pragma unroll
            for (int bb = 0; bb < 4; ++bb)
                xv[bb] = *reinterpret_cast<const float4*>(
                    xr + (size_t)bb * SSEQ * EE + e);
            unsigned long long pk[2][4];
            pk[0][0] = pack2(xv[0].x, xv[1].x);  pk[1][0] = pack2(xv[2].x, xv[3].x);
            pk[0][1] = pack2(xv[0].y, xv[1].y);  pk[1][1] = pack2(xv[2].y, xv[3].y);
            pk[0][2] = pack2(xv[0].z, xv[1].z);  pk[1][2] = pack2(xv[2].z, xv[3].z);
            pk[0][3] = pack2(xv[0].w, xv[1].w);  pk[1][3] = pack2(xv[2].w, xv[3].w);
#pragma unroll
            for (int v = 0; v < 7; ++v) {
                const float4 wv = *reinterpret_cast<const float4*>(
                    wr + (size_t)v * WE + e);
                const float* wk = &wv.x;
#pragma unroll
                for (int k = 0; k < 4; ++k) {
                    const unsigned long long dw = pack_dup(wk[k]);
                    ffma2(acc[v][0], dw, pk[0][k]);
                    ffma2(acc[v][1], dw, pk[1][k]);
                }
            }
        }
    }

    // In-warp butterfly (both packed halves = 2 batches stay separate).
#pragma unroll
    for (int v = 0; v < 7; ++v)
#pragma unroll
        for (int pr = 0; pr < 2; ++pr) {
            unsigned long long s = acc[v][pr];
#pragma unroll
            for (int o = 16; o > 0; o >>= 1)
                s = add2(s, shfl_xor_u64(s, o));
            acc[v][pr] = s;
        }
    if (lane == 0) {
#pragma unroll
        for (int v = 0; v < 7; ++v) {
            s_red[warp * 14 + v * 2 + 0] = acc[v][0];
            s_red[warp * 14 + v * 2 + 1] = acc[v][1];
        }
    }
    __syncthreads();

    // Warps 2*bg and 2*bg+1 hold batch-group bg. Lane tid<28 -> (bg, v).
    if (tid < 28) {
        const int bgx = tid / 7;
        const int v   = tid % 7;
        const unsigned long long a0 =
            add2(s_red[(bgx * 2) * 14 + v * 2 + 0],
                 s_red[(bgx * 2 + 1) * 14 + v * 2 + 0]);
        const unsigned long long a1 =
            add2(s_red[(bgx * 2) * 14 + v * 2 + 1],
                 s_red[(bgx * 2 + 1) * 14 + v * 2 + 1]);
        const float bz = bias[t * 7 + v];
        const float2 q0 = unpack2(a0);
        const float2 q1 = unpack2(a1);
        const int gb = (bgx << 2) * (SSEQ * 8) + t * 8 + v;
        g_gates[gb]                  = 1.0f / (1.0f + __expf(-(q0.x + bz)));
        g_gates[gb + 1 * SSEQ * 8]   = 1.0f / (1.0f + __expf(-(q0.y + bz)));
        g_gates[gb + 2 * SSEQ * 8]   = 1.0f / (1.0f + __expf(-(q1.x + bz)));
        g_gates[gb + 3 * SSEQ * 8]   = 1.0f / (1.0f + __expf(-(q1.y + bz)));
    }
}

// ----------------------------------------------------------------------
// Kernel 2: out[b,t,e] = tanh( sum_w gates[b,t,w] * x[b,t+w-3,e] )
// Warp = (b, 128-float e-chunk, 32 consecutive t). Sliding 7-tap window.
// ----------------------------------------------------------------------
__global__ void __launch_bounds__(256, 3)
out_kernel(const float* __restrict__ x, float* __restrict__ out) {
    const int wg   = blockIdx.x * 8 + (threadIdx.x >> 5);
    const int lane = threadIdx.x & 31;
    const int b    = wg >> 8;             // 16
    const int rem  = wg & 255;
    const int ec   = rem >> 5;            // 8 e-chunks
    const int ts   = rem & 31;            // 32 t-ranges
    const int t0   = ts << 5;             // 32 t's per warp
    const int e    = (ec << 7) + (lane << 2);

    const float* xb = x + (size_t)b * SSEQ * EE + e;
    const float* gb = g_gates + b * (SSEQ * 8);
    float* ob       = out + (size_t)b * SSEQ * EE + e;

    unsigned long long win[7][2];         // win[w] = x[t + w - 3] (2 ull = f4)
#pragma unroll
    for (int k = 0; k < 6; ++k) {
        const int r = t0 + k - 3;
        if (r >= 0) {
            const ulonglong2 xv = *reinterpret_cast<const ulonglong2*>(
                xb + (size_t)r * EE);
            win[k][0] = xv.x; win[k][1] = xv.y;
        } else { win[k][0] = 0ull; win[k][1] = 0ull; }
    }

    for (int tt = 0; tt < 32; ++tt) {
        const int t  = t0 + tt;
        const int rn = t + 3;
        if (rn < SSEQ) {
            const ulonglong2 xv = *reinterpret_cast<const ulonglong2*>(
                xb + (size_t)rn * EE);
            win[6][0] = xv.x; win[6][1] = xv.y;
        } else { win[6][0] = 0ull; win[6][1] = 0ull; }

        const float4 g0 = *reinterpret_cast<const float4*>(gb + t * 8);
        const float4 g1 = *reinterpret_cast<const float4*>(gb + t * 8 + 4);

        unsigned long long o0 = 0ull, o1 = 0ull;
        unsigned long long dg;
        dg = pack_dup(g0.x); ffma2(o0, dg, win[0][0]); ffma2(o1, dg, win[0][1]);
        dg = pack_dup(g0.y); ffma2(o0, dg, win[1][0]); ffma2(o1, dg, win[1][1]);
        dg = pack_dup(g0.z); ffma2(o0, dg, win[2][0]); ffma2(o1, dg, win[2][1]);
        dg = pack_dup(g0.w); ffma2(o0, dg, win[3][0]); ffma2(o1, dg, win[3][1]);
        dg = pack_dup(g1.x); ffma2(o0, dg, win[4][0]); ffma2(o1, dg, win[4][1]);
        dg = pack_dup(g1.y); ffma2(o0, dg, win[5][0]); ffma2(o1, dg, win[5][1]);
        dg = pack_dup(g1.z); ffma2(o0, dg, win[6][0]); ffma2(o1, dg, win[6][1]);

        const float2 p0 = unpack2(o0);
        const float2 p1 = unpack2(o1);
        float4 ov;
        ov.x = tanh_ap(p0.x);
        ov.y = tanh_ap(p0.y);
        ov.z = tanh_ap(p1.x);
        ov.w = tanh_ap(p1.y);
        *reinterpret_cast<float4*>(ob + (size_t)t * EE) = ov;

#pragma unroll
        for (int k = 0; k < 6; ++k) {
            win[k][0] = win[k + 1][0];
            win[k][1] = win[k + 1][1];
        }
    }
}

extern "C" void kernel_launch(void* const* d_in, const int* in_sizes, int n_in,
                              void* d_out, int out_size) {
    const float* x    = (const float*)d_in[0];
    const float* wgt  = (const float*)d_in[1];
    const float* bias = (const float*)d_in[2];
    float* out        = (float*)d_out;

    gates_kernel<<<SSEQ, 256>>>(x, wgt, bias);
    out_kernel<<<(BB * 8 * 32) / 8, 256>>>(x, out);
}